// round 9
// baseline (speedup 1.0000x reference)
#include <cuda_runtime.h>
#include <cstdint>

#define Bb 2
#define Hh 16
#define Ss 2048
#define Dd 64
#define BH (Bb*Hh)
#define SCALE 0.125f

typedef unsigned long long ull;

// ---------------- global scratch ----------------
__device__ unsigned int g_maskbits[(size_t)Bb * Ss * Ss / 32];
#define TILE_ULL 1024
__device__ ull gKhi[(size_t)BH * 32 * TILE_ULL];
__device__ ull gKlo[(size_t)BH * 32 * TILE_ULL];
__device__ ull gVhi[(size_t)BH * 32 * TILE_ULL];
__device__ ull gVlo[(size_t)BH * 32 * TILE_ULL];

__global__ void pack_mask_kernel(const int* __restrict__ masks)
{
    int e = blockIdx.x * 256 + threadIdx.x;
    int val = masks[e] != 0;
    unsigned bal = __ballot_sync(0xFFFFFFFFu, val);
    if ((threadIdx.x & 31) == 0) g_maskbits[e >> 5] = bal;
}

// ---------------- helpers ----------------
__device__ __forceinline__ uint32_t packpair(float s0, float s1) {
    uint32_t p;  // low 16 = s0, high 16 = s1
    asm("cvt.rn.bf16x2.f32 %0, %1, %2;" : "=r"(p) : "f"(s1), "f"(s0));
    return p;
}
__device__ __forceinline__ uint32_t packhi(float s0, float s1, float& h0, float& h1) {
    uint32_t p = packpair(s0, s1);
    h0 = __uint_as_float(p << 16);
    h1 = __uint_as_float(p & 0xFFFF0000u);
    return p;
}
__device__ __forceinline__ void mma16(float4& d, uint32_t a0, uint32_t a1, uint32_t a2,
                                      uint32_t a3, uint32_t b0, uint32_t b1)
{
    asm volatile(
        "mma.sync.aligned.m16n8k16.row.col.f32.bf16.bf16.f32 "
        "{%0,%1,%2,%3}, {%4,%5,%6,%7}, {%8,%9}, {%0,%1,%2,%3};"
        : "+f"(d.x), "+f"(d.y), "+f"(d.z), "+f"(d.w)
        : "r"(a0), "r"(a1), "r"(a2), "r"(a3), "r"(b0), "r"(b1));
}
__device__ __forceinline__ float ex2m(float x) {
    float r;
    asm("ex2.approx.f32 %0, %1;" : "=f"(r) : "f"(x));
    return r;
}
__device__ __forceinline__ uint2 ldg64(const ull* p) {
    uint2 r;
    asm("ld.global.nc.v2.u32 {%0,%1}, [%2];" : "=r"(r.x), "=r"(r.y) : "l"(p));
    return r;
}
#define L2E 1.4426950408889634f

// fragment-major granule index within an 8KB plane: [ks][j][g*4+tig]
__device__ __forceinline__ int fidx(int ks, int j, int g4t) {
    return (ks * 8 + j) * 32 + g4t;
}

// ---------------- prepasses (fragment-major output) ----------------
__global__ void split_k_kernel(const float* __restrict__ k)
{
    int idx = blockIdx.x * 256 + threadIdx.x;    // BH*2048*16
    int gidx = idx & 15;
    int tglob = (idx >> 4) & 2047;
    int bh = idx >> 15;
    int ks = gidx >> 2, tig = gidx & 3;
    const float* kr = k + ((size_t)bh * Ss + tglob) * Dd + 16 * ks + 2 * tig;
    float2 p0 = *(const float2*)kr;
    float2 p1 = *(const float2*)(kr + 8);
    float h00, h01, h10, h11;
    uint32_t b0h = packhi(p0.x, p0.y, h00, h01);
    uint32_t b1h = packhi(p1.x, p1.y, h10, h11);
    uint32_t b0l = packpair(p0.x - h00, p0.y - h01);
    uint32_t b1l = packpair(p1.x - h10, p1.y - h11);
    int kt = tglob >> 6;
    int tl = tglob & 63;
    int j = tl >> 3, g = tl & 7;
    size_t base = ((size_t)bh * 32 + kt) * TILE_ULL + fidx(ks, j, g * 4 + tig);
    gKhi[base] = (ull)b0h | ((ull)b1h << 32);
    gKlo[base] = (ull)b0l | ((ull)b1l << 32);
}

__global__ void split_vt_kernel(const float* __restrict__ v)
{
    int idx = blockIdx.x * 256 + threadIdx.x;    // BH*32*16*64
    int d  = idx & 63;
    int gidx = (idx >> 6) & 15;
    int kt = (idx >> 10) & 31;
    int bh = idx >> 15;
    int ks = gidx >> 2, tig = gidx & 3;
    int t0 = kt * 64 + 16 * ks + 2 * tig;
    const float* vb = v + (size_t)bh * Ss * Dd + d;
    float v0 = vb[(size_t)t0 * Dd];
    float v1 = vb[(size_t)(t0 + 1) * Dd];
    float v2 = vb[(size_t)(t0 + 8) * Dd];
    float v3 = vb[(size_t)(t0 + 9) * Dd];
    float h0, h1, h2, h3;
    uint32_t b0h = packhi(v0, v1, h0, h1);
    uint32_t b1h = packhi(v2, v3, h2, h3);
    uint32_t b0l = packpair(v0 - h0, v1 - h1);
    uint32_t b1l = packpair(v2 - h2, v3 - h3);
    int j = d >> 3, g = d & 7;
    size_t base = ((size_t)bh * 32 + kt) * TILE_ULL + fidx(ks, j, g * 4 + tig);
    gVhi[base] = (ull)b0h | ((ull)b1h << 32);
    gVlo[base] = (ull)b0l | ((ull)b1l << 32);
}

#define SMEM_TOTAL 512    // sInv only

__global__ void __launch_bounds__(256, 2)
sdpa_main_kernel(const float* __restrict__ q, float* __restrict__ out)
{
    __shared__ float sInv[128];

    const int tid  = threadIdx.x;
    const int lane = tid & 31;
    const int w    = tid >> 5;
    const int g    = lane >> 2;
    const int tig  = lane & 3;

    const int bh = blockIdx.y;
    const int b  = bh >> 4;
    const int s0 = blockIdx.x * 128;

    const float* qg = q + ((size_t)bh * Ss + s0) * Dd;
    float* outg = out + ((size_t)bh * Ss + s0) * Dd;
    float* attg = out + (size_t)BH * Ss * Dd + ((size_t)bh * Ss + s0) * Ss;

    const size_t tilebase = (size_t)bh * 32;

    // ---- Q fragments: per-thread direct gmem loads (one-time) ----
    const int r0 = w * 16 + g;
    uint2 qh[4][2], ql[4][2];
    {
        const float* q0 = qg + (size_t)r0 * Dd;
        const float* q8 = qg + (size_t)(r0 + 8) * Dd;
        #pragma unroll
        for (int ks = 0; ks < 4; ++ks) {
            int c = 16 * ks + 2 * tig;
            #pragma unroll
            for (int half = 0; half < 2; ++half) {
                const float* qr = half ? q8 : q0;
                float2 p0 = *(const float2*)(qr + c);
                float2 p1 = *(const float2*)(qr + c + 8);
                float h00, h01, h10, h11;
                uint32_t b0h = packhi(p0.x, p0.y, h00, h01);
                uint32_t b1h = packhi(p1.x, p1.y, h10, h11);
                qh[ks][half] = make_uint2(b0h, b1h);
                ql[ks][half] = make_uint2(packpair(p0.x - h00, p0.y - h01),
                                          packpair(p1.x - h10, p1.y - h11));
            }
        }
    }

    const ull* m64 = (const ull*)g_maskbits;
    const size_t mrow0 = ((size_t)b * Ss + s0 + r0) * (Ss / 64);
    const size_t mrow1 = mrow0 + 8 * (Ss / 64);

    float rs0 = 0.f, rs1 = 0.f;
    float4 po[8];
    #pragma unroll
    for (int j = 0; j < 8; ++j) po[j] = make_float4(0.f, 0.f, 0.f, 0.f);

    float* att0 = attg + (size_t)r0 * Ss;
    float* att1 = attg + (size_t)(r0 + 8) * Ss;

    // base pointers into fragment-major planes (advance 1024 ull per chunk)
    const ull* kH = gKhi + tilebase * TILE_ULL + lane;
    const ull* kL = gKlo + tilebase * TILE_ULL + lane;
    const ull* vH = gVhi + tilebase * TILE_ULL + lane;
    const ull* vL = gVlo + tilebase * TILE_ULL + lane;

    // NO barriers in this loop: warps run fully decoupled.
    for (int kt = 0; kt < 32; ++kt) {
        ull mw0 = m64[mrow0 + kt];
        ull mw1 = m64[mrow1 + kt];

        // ---- QK: 128x64 scores via bf16x3 (B frags via contiguous LDG.64) ----
        float4 cf[8];
        #pragma unroll
        for (int j = 0; j < 8; ++j) cf[j] = make_float4(0.f, 0.f, 0.f, 0.f);

        #pragma unroll
        for (int ks = 0; ks < 4; ++ks) {
            uint2 aH0 = qh[ks][0], aH8 = qh[ks][1];
            uint2 aL0 = ql[ks][0], aL8 = ql[ks][1];
            #pragma unroll
            for (int j = 0; j < 8; ++j) {
                int fo = (ks * 8 + j) * 32;
                uint2 bH = ldg64(kH + fo);
                uint2 bL = ldg64(kL + fo);
                mma16(cf[j], aH0.x, aH8.x, aH0.y, aH8.y, bH.x, bH.y);
                mma16(cf[j], aH0.x, aH8.x, aH0.y, aH8.y, bL.x, bL.y);
                mma16(cf[j], aL0.x, aL8.x, aL0.y, aL8.y, bH.x, bH.y);
            }
        }

        // ---- epilogue fused with PV (C-frag -> A-frag identity) ----
        const int t0k = kt * 64;
        #pragma unroll
        for (int ks2 = 0; ks2 < 4; ++ks2) {
            uint32_t pa[2][2], pb[2][2];
            #pragma unroll
            for (int u = 0; u < 2; ++u) {
                int j = 2 * ks2 + u;
                int c0 = 8 * j + 2 * tig;
                float4 c = cf[j];
                float s00 = ((mw0 >> c0) & 1ull)       ? c.x * SCALE : -1e-12f;
                float s01 = ((mw0 >> (c0 + 1)) & 1ull) ? c.y * SCALE : -1e-12f;
                float s10 = ((mw1 >> c0) & 1ull)       ? c.z * SCALE : -1e-12f;
                float s11 = ((mw1 >> (c0 + 1)) & 1ull) ? c.w * SCALE : -1e-12f;
                float e00 = ex2m(s00 * L2E), e01 = ex2m(s01 * L2E);
                float e10 = ex2m(s10 * L2E), e11 = ex2m(s11 * L2E);
                rs0 += e00 + e01; rs1 += e10 + e11;
                *(float2*)(att0 + t0k + c0) = make_float2(e00, e01);
                *(float2*)(att1 + t0k + c0) = make_float2(e10, e11);
                float h0, h1;
                pa[u][0] = packhi(s00, s01, h0, h1);
                pa[u][1] = packpair(s00 - h0, s01 - h1);
                pb[u][0] = packhi(s10, s11, h0, h1);
                pb[u][1] = packpair(s10 - h0, s11 - h1);
            }
            #pragma unroll
            for (int j = 0; j < 8; ++j) {
                int fo = (ks2 * 8 + j) * 32;
                uint2 bH = ldg64(vH + fo);
                uint2 bL = ldg64(vL + fo);
                mma16(po[j], pa[0][0], pb[0][0], pa[1][0], pb[1][0], bH.x, bH.y);
                mma16(po[j], pa[0][0], pb[0][0], pa[1][0], pb[1][0], bL.x, bL.y);
                mma16(po[j], pa[0][1], pb[0][1], pa[1][1], pb[1][1], bH.x, bH.y);
            }
        }

        kH += TILE_ULL; kL += TILE_ULL; vH += TILE_ULL; vL += TILE_ULL;
    }

    // ---- write output ----
    #pragma unroll
    for (int j = 0; j < 8; ++j) {
        int c0 = 8 * j + 2 * tig;
        *(float2*)(outg + (size_t)r0 * Dd + c0)       = make_float2(po[j].x, po[j].y);
        *(float2*)(outg + (size_t)(r0 + 8) * Dd + c0) = make_float2(po[j].z, po[j].w);
    }

    // ---- rowsum reduce + normalize att ----
    rs0 += __shfl_xor_sync(0xFFFFFFFFu, rs0, 1);
    rs0 += __shfl_xor_sync(0xFFFFFFFFu, rs0, 2);
    rs1 += __shfl_xor_sync(0xFFFFFFFFu, rs1, 1);
    rs1 += __shfl_xor_sync(0xFFFFFFFFu, rs1, 2);
    if (tig == 0) {
        sInv[r0]     = 1.f / rs0;
        sInv[r0 + 8] = 1.f / rs1;
    }
    __syncthreads();

    for (int r = 0; r < 128; ++r) {
        float iv = sInv[r];
        float* row = attg + (size_t)r * Ss + tid * 8;
        float4 a = *(const float4*)(row);
        float4 c = *(const float4*)(row + 4);
        a.x *= iv; a.y *= iv; a.z *= iv; a.w *= iv;
        c.x *= iv; c.y *= iv; c.z *= iv; c.w *= iv;
        *(float4*)(row)     = a;
        *(float4*)(row + 4) = c;
    }
}

extern "C" void kernel_launch(void* const* d_in, const int* in_sizes, int n_in,
                              void* d_out, int out_size)
{
    const float* q = (const float*)d_in[0];
    const float* k = (const float*)d_in[1];
    const float* v = (const float*)d_in[2];
    const int* masks = (const int*)d_in[3];
    float* out = (float*)d_out;

    pack_mask_kernel<<<(Bb * Ss * Ss) / 256, 256>>>(masks);
    split_k_kernel<<<(BH * Ss * 16) / 256, 256>>>(k);
    split_vt_kernel<<<(BH * 32 * 16 * 64) / 256, 256>>>(v);

    dim3 grid(Ss / 128, BH);   // (16, 32)
    sdpa_main_kernel<<<grid, 256>>>(q, out);
}

// round 10
// speedup vs baseline: 2.5149x; 2.5149x over previous
#include <cuda_runtime.h>
#include <cstdint>

#define Bb 2
#define Hh 16
#define Ss 2048
#define Dd 64
#define BH (Bb*Hh)
#define SCALE 0.125f

typedef unsigned long long ull;

// ---------------- global scratch ----------------
__device__ unsigned int g_maskbits[(size_t)Bb * Ss * Ss / 32];
#define TILE_U4 1024      // uint4 granules per 16KB chunk-plane
__device__ uint4 gK4[(size_t)BH * 32 * TILE_U4];   // 16 MB
__device__ uint4 gV4[(size_t)BH * 32 * TILE_U4];   // 16 MB

__global__ void pack_mask_kernel(const int* __restrict__ masks)
{
    int e = blockIdx.x * 256 + threadIdx.x;
    int val = masks[e] != 0;
    unsigned bal = __ballot_sync(0xFFFFFFFFu, val);
    if ((threadIdx.x & 31) == 0) g_maskbits[e >> 5] = bal;
}

// ---------------- helpers ----------------
__device__ __forceinline__ uint32_t smem_u32(const void* p) {
    uint32_t a;
    asm("{ .reg .u64 t; cvta.to.shared.u64 t, %1; cvt.u32.u64 %0, t; }" : "=r"(a) : "l"(p));
    return a;
}
__device__ __forceinline__ uint32_t packpair(float s0, float s1) {
    uint32_t p;  // low 16 = s0, high 16 = s1
    asm("cvt.rn.bf16x2.f32 %0, %1, %2;" : "=r"(p) : "f"(s1), "f"(s0));
    return p;
}
__device__ __forceinline__ uint32_t packhi(float s0, float s1, float& h0, float& h1) {
    uint32_t p = packpair(s0, s1);
    h0 = __uint_as_float(p << 16);
    h1 = __uint_as_float(p & 0xFFFF0000u);
    return p;
}
__device__ __forceinline__ void mma16(float4& d, uint32_t a0, uint32_t a1, uint32_t a2,
                                      uint32_t a3, uint32_t b0, uint32_t b1)
{
    asm volatile(
        "mma.sync.aligned.m16n8k16.row.col.f32.bf16.bf16.f32 "
        "{%0,%1,%2,%3}, {%4,%5,%6,%7}, {%8,%9}, {%0,%1,%2,%3};"
        : "+f"(d.x), "+f"(d.y), "+f"(d.z), "+f"(d.w)
        : "r"(a0), "r"(a1), "r"(a2), "r"(a3), "r"(b0), "r"(b1));
}
__device__ __forceinline__ float ex2m(float x) {
    float r;
    asm("ex2.approx.f32 %0, %1;" : "=f"(r) : "f"(x));
    return r;
}
#define L2E 1.4426950408889634f

// ---------------- prepasses: fused hi/lo fragment-major uint4 granules ----------------
__global__ void split_k_kernel(const float* __restrict__ k)
{
    int idx = blockIdx.x * 256 + threadIdx.x;    // BH*2048*16
    int gidx = idx & 15;
    int tglob = (idx >> 4) & 2047;
    int bh = idx >> 15;
    int ks = gidx >> 2, tig = gidx & 3;
    const float* kr = k + ((size_t)bh * Ss + tglob) * Dd + 16 * ks + 2 * tig;
    float2 p0 = *(const float2*)kr;
    float2 p1 = *(const float2*)(kr + 8);
    float h00, h01, h10, h11;
    uint32_t b0h = packhi(p0.x, p0.y, h00, h01);
    uint32_t b1h = packhi(p1.x, p1.y, h10, h11);
    uint32_t b0l = packpair(p0.x - h00, p0.y - h01);
    uint32_t b1l = packpair(p1.x - h10, p1.y - h11);
    int kt = tglob >> 6;
    int tl = tglob & 63;
    int j = tl >> 3, g = tl & 7;
    gK4[((size_t)bh * 32 + kt) * TILE_U4 + (ks * 8 + j) * 32 + g * 4 + tig] =
        make_uint4(b0h, b1h, b0l, b1l);
}

__global__ void split_vt_kernel(const float* __restrict__ v)
{
    int idx = blockIdx.x * 256 + threadIdx.x;    // BH*32*16*64
    int d  = idx & 63;
    int gidx = (idx >> 6) & 15;
    int kt = (idx >> 10) & 31;
    int bh = idx >> 15;
    int ks = gidx >> 2, tig = gidx & 3;
    int t0 = kt * 64 + 16 * ks + 2 * tig;
    const float* vb = v + (size_t)bh * Ss * Dd + d;
    float v0 = vb[(size_t)t0 * Dd];
    float v1 = vb[(size_t)(t0 + 1) * Dd];
    float v2 = vb[(size_t)(t0 + 8) * Dd];
    float v3 = vb[(size_t)(t0 + 9) * Dd];
    float h0, h1, h2, h3;
    uint32_t b0h = packhi(v0, v1, h0, h1);
    uint32_t b1h = packhi(v2, v3, h2, h3);
    uint32_t b0l = packpair(v0 - h0, v1 - h1);
    uint32_t b1l = packpair(v2 - h2, v3 - h3);
    int j = d >> 3, g = d & 7;
    gV4[((size_t)bh * 32 + kt) * TILE_U4 + (ks * 8 + j) * 32 + g * 4 + tig] =
        make_uint4(b0h, b1h, b0l, b1l);
}

// ---------------- smem: 3-stage ring, stage = [K 16KB][V 16KB] ----------------
#define SINV 98304u
#define SMEM_TOTAL (98304 + 512)

__global__ void __launch_bounds__(256, 2)
sdpa_main_kernel(const float* __restrict__ q, float* __restrict__ out)
{
    extern __shared__ char smc[];
    const uint32_t sb = smem_u32(smc);
    float* sInv = (float*)(smc + SINV);

    const int tid  = threadIdx.x;
    const int lane = tid & 31;
    const int w    = tid >> 5;
    const int g    = lane >> 2;
    const int tig  = lane & 3;

    const int bh = blockIdx.y;
    const int b  = bh >> 4;
    const int s0 = blockIdx.x * 128;

    const float* qg = q + ((size_t)bh * Ss + s0) * Dd;
    float* outg = out + ((size_t)bh * Ss + s0) * Dd;
    float* attg = out + (size_t)BH * Ss * Dd + ((size_t)bh * Ss + s0) * Ss;

    const size_t tilebase = (size_t)bh * 32;

    auto issue = [&](int kt) {
        uint32_t dstb = sb + (uint32_t)(kt % 3) * 32768u;
        const char* srcK = (const char*)(gK4 + (tilebase + kt) * TILE_U4);
        const char* srcV = (const char*)(gV4 + (tilebase + kt) * TILE_U4);
        #pragma unroll
        for (int i = 0; i < 4; ++i) {
            int off = (tid + i * 256) * 16;
            asm volatile("cp.async.cg.shared.global [%0], [%1], 16;"
                         :: "r"(dstb + off), "l"(srcK + off));
        }
        #pragma unroll
        for (int i = 0; i < 4; ++i) {
            int off = (tid + i * 256) * 16;
            asm volatile("cp.async.cg.shared.global [%0], [%1], 16;"
                         :: "r"(dstb + 16384u + off), "l"(srcV + off));
        }
        asm volatile("cp.async.commit_group;");
    };

    issue(0);
    issue(1);

    // ---- Q fragments: per-thread direct gmem loads (one-time) ----
    const int r0 = w * 16 + g;
    uint2 qh[4][2], ql[4][2];
    {
        const float* q0 = qg + (size_t)r0 * Dd;
        const float* q8 = qg + (size_t)(r0 + 8) * Dd;
        #pragma unroll
        for (int ks = 0; ks < 4; ++ks) {
            int c = 16 * ks + 2 * tig;
            #pragma unroll
            for (int half = 0; half < 2; ++half) {
                const float* qr = half ? q8 : q0;
                float2 p0 = *(const float2*)(qr + c);
                float2 p1 = *(const float2*)(qr + c + 8);
                float h00, h01, h10, h11;
                uint32_t b0h = packhi(p0.x, p0.y, h00, h01);
                uint32_t b1h = packhi(p1.x, p1.y, h10, h11);
                qh[ks][half] = make_uint2(b0h, b1h);
                ql[ks][half] = make_uint2(packpair(p0.x - h00, p0.y - h01),
                                          packpair(p1.x - h10, p1.y - h11));
            }
        }
    }

    const ull* m64 = (const ull*)g_maskbits;
    const size_t mrow0 = ((size_t)b * Ss + s0 + r0) * (Ss / 64);
    const size_t mrow1 = mrow0 + 8 * (Ss / 64);

    float rs0 = 0.f, rs1 = 0.f;
    float4 po[8];
    #pragma unroll
    for (int j = 0; j < 8; ++j) po[j] = make_float4(0.f, 0.f, 0.f, 0.f);

    float* att0 = attg + (size_t)r0 * Ss;
    float* att1 = attg + (size_t)(r0 + 8) * Ss;

    for (int kt = 0; kt < 32; ++kt) {
        if (kt < 31) { asm volatile("cp.async.wait_group 1;"); }
        else         { asm volatile("cp.async.wait_group 0;"); }
        __syncthreads();
        if (kt < 30) issue(kt + 2);

        const uint4* kb4 = (const uint4*)(smc + (kt % 3) * 32768);
        const uint4* vb4 = kb4 + 1024;

        ull mw0 = m64[mrow0 + kt];
        ull mw1 = m64[mrow1 + kt];

        // ---- QK: 128x64 scores via bf16x3; one LDS.128 feeds 3 mma ----
        float4 cf[8];
        #pragma unroll
        for (int j = 0; j < 8; ++j) cf[j] = make_float4(0.f, 0.f, 0.f, 0.f);

        #pragma unroll
        for (int ks = 0; ks < 4; ++ks) {
            uint2 aH0 = qh[ks][0], aH8 = qh[ks][1];
            uint2 aL0 = ql[ks][0], aL8 = ql[ks][1];
            #pragma unroll
            for (int j = 0; j < 8; ++j) {
                uint4 f = kb4[(ks * 8 + j) * 32 + lane];
                mma16(cf[j], aH0.x, aH8.x, aH0.y, aH8.y, f.x, f.y);
                mma16(cf[j], aH0.x, aH8.x, aH0.y, aH8.y, f.z, f.w);
                mma16(cf[j], aL0.x, aL8.x, aL0.y, aL8.y, f.x, f.y);
            }
        }

        // ---- epilogue fused with PV (C-frag -> A-frag identity) ----
        const int t0k = kt * 64;
        #pragma unroll
        for (int ks2 = 0; ks2 < 4; ++ks2) {
            uint32_t pa[2][2], pb[2][2];
            #pragma unroll
            for (int u = 0; u < 2; ++u) {
                int j = 2 * ks2 + u;
                int c0 = 8 * j + 2 * tig;
                float4 c = cf[j];
                float s00 = ((mw0 >> c0) & 1ull)       ? c.x * SCALE : -1e-12f;
                float s01 = ((mw0 >> (c0 + 1)) & 1ull) ? c.y * SCALE : -1e-12f;
                float s10 = ((mw1 >> c0) & 1ull)       ? c.z * SCALE : -1e-12f;
                float s11 = ((mw1 >> (c0 + 1)) & 1ull) ? c.w * SCALE : -1e-12f;
                float e00 = ex2m(s00 * L2E), e01 = ex2m(s01 * L2E);
                float e10 = ex2m(s10 * L2E), e11 = ex2m(s11 * L2E);
                rs0 += e00 + e01; rs1 += e10 + e11;
                *(float2*)(att0 + t0k + c0) = make_float2(e00, e01);
                *(float2*)(att1 + t0k + c0) = make_float2(e10, e11);
                float h0, h1;
                pa[u][0] = packhi(s00, s01, h0, h1);
                pa[u][1] = packpair(s00 - h0, s01 - h1);
                pb[u][0] = packhi(s10, s11, h0, h1);
                pb[u][1] = packpair(s10 - h0, s11 - h1);
            }
            #pragma unroll
            for (int j = 0; j < 8; ++j) {
                uint4 f = vb4[(ks2 * 8 + j) * 32 + lane];
                mma16(po[j], pa[0][0], pb[0][0], pa[1][0], pb[1][0], f.x, f.y);
                mma16(po[j], pa[0][0], pb[0][0], pa[1][0], pb[1][0], f.z, f.w);
                mma16(po[j], pa[0][1], pb[0][1], pa[1][1], pb[1][1], f.x, f.y);
            }
        }
        __syncthreads();   // all warps done with stage (kt%3) before refill
    }

    // ---- write output ----
    #pragma unroll
    for (int j = 0; j < 8; ++j) {
        int c0 = 8 * j + 2 * tig;
        *(float2*)(outg + (size_t)r0 * Dd + c0)       = make_float2(po[j].x, po[j].y);
        *(float2*)(outg + (size_t)(r0 + 8) * Dd + c0) = make_float2(po[j].z, po[j].w);
    }

    // ---- rowsum reduce + normalize att ----
    rs0 += __shfl_xor_sync(0xFFFFFFFFu, rs0, 1);
    rs0 += __shfl_xor_sync(0xFFFFFFFFu, rs0, 2);
    rs1 += __shfl_xor_sync(0xFFFFFFFFu, rs1, 1);
    rs1 += __shfl_xor_sync(0xFFFFFFFFu, rs1, 2);
    if (tig == 0) {
        sInv[r0]     = 1.f / rs0;
        sInv[r0 + 8] = 1.f / rs1;
    }
    __syncthreads();

    for (int r = 0; r < 128; ++r) {
        float iv = sInv[r];
        float* row = attg + (size_t)r * Ss + tid * 8;
        float4 a = *(const float4*)(row);
        float4 c = *(const float4*)(row + 4);
        a.x *= iv; a.y *= iv; a.z *= iv; a.w *= iv;
        c.x *= iv; c.y *= iv; c.z *= iv; c.w *= iv;
        *(float4*)(row)     = a;
        *(float4*)(row + 4) = c;
    }
}

extern "C" void kernel_launch(void* const* d_in, const int* in_sizes, int n_in,
                              void* d_out, int out_size)
{
    const float* q = (const float*)d_in[0];
    const float* k = (const float*)d_in[1];
    const float* v = (const float*)d_in[2];
    const int* masks = (const int*)d_in[3];
    float* out = (float*)d_out;

    pack_mask_kernel<<<(Bb * Ss * Ss) / 256, 256>>>(masks);
    split_k_kernel<<<(BH * Ss * 16) / 256, 256>>>(k);
    split_vt_kernel<<<(BH * 32 * 16 * 64) / 256, 256>>>(v);

    cudaFuncSetAttribute(sdpa_main_kernel,
                         cudaFuncAttributeMaxDynamicSharedMemorySize, SMEM_TOTAL);

    dim3 grid(Ss / 128, BH);   // (16, 32)
    sdpa_main_kernel<<<grid, 256, SMEM_TOTAL>>>(q, out);
}

// round 11
// speedup vs baseline: 3.2343x; 1.2861x over previous
#include <cuda_runtime.h>
#include <cstdint>

#define Bb 2
#define Hh 16
#define Ss 2048
#define Dd 64
#define BH (Bb*Hh)
#define SCALE 0.125f

typedef unsigned long long ull;

// ---------------- global scratch ----------------
__device__ unsigned int g_maskbits[(size_t)Bb * Ss * Ss / 32];
#define TILE_U2 1024      // uint2 granules per 8KB chunk-plane
__device__ uint2 gK2[(size_t)BH * 32 * TILE_U2];   // 8 MB (fp16 pairs)
__device__ uint2 gV2[(size_t)BH * 32 * TILE_U2];   // 8 MB

__global__ void pack_mask_kernel(const int* __restrict__ masks)
{
    int e = blockIdx.x * 256 + threadIdx.x;
    int val = masks[e] != 0;
    unsigned bal = __ballot_sync(0xFFFFFFFFu, val);
    if ((threadIdx.x & 31) == 0) g_maskbits[e >> 5] = bal;
}

// ---------------- helpers ----------------
__device__ __forceinline__ uint32_t smem_u32(const void* p) {
    uint32_t a;
    asm("{ .reg .u64 t; cvta.to.shared.u64 t, %1; cvt.u32.u64 %0, t; }" : "=r"(a) : "l"(p));
    return a;
}
// fp16x2 pack: low half = s0, high half = s1
__device__ __forceinline__ uint32_t packf16(float s0, float s1) {
    uint32_t p;
    asm("cvt.rn.f16x2.f32 %0, %1, %2;" : "=r"(p) : "f"(s1), "f"(s0));
    return p;
}
// pack and also return the rounded values as fp32
__device__ __forceinline__ uint32_t packf16hi(float s0, float s1, float& h0, float& h1) {
    uint32_t p = packf16(s0, s1);
    asm("{ .reg .f16 a,b; mov.b32 {a,b}, %2; cvt.f32.f16 %0, a; cvt.f32.f16 %1, b; }"
        : "=f"(h0), "=f"(h1) : "r"(p));
    return p;
}
__device__ __forceinline__ void mma16f(float4& d, uint32_t a0, uint32_t a1, uint32_t a2,
                                       uint32_t a3, uint32_t b0, uint32_t b1)
{
    asm volatile(
        "mma.sync.aligned.m16n8k16.row.col.f32.f16.f16.f32 "
        "{%0,%1,%2,%3}, {%4,%5,%6,%7}, {%8,%9}, {%0,%1,%2,%3};"
        : "+f"(d.x), "+f"(d.y), "+f"(d.z), "+f"(d.w)
        : "r"(a0), "r"(a1), "r"(a2), "r"(a3), "r"(b0), "r"(b1));
}
__device__ __forceinline__ float ex2m(float x) {
    float r;
    asm("ex2.approx.f32 %0, %1;" : "=f"(r) : "f"(x));
    return r;
}
#define L2E 1.4426950408889634f

// ---------------- prepasses: fp16-rounded fragment-major granules ----------------
__global__ void split_k_kernel(const float* __restrict__ k)
{
    int idx = blockIdx.x * 256 + threadIdx.x;    // BH*2048*16
    int gidx = idx & 15;
    int tglob = (idx >> 4) & 2047;
    int bh = idx >> 15;
    int ks = gidx >> 2, tig = gidx & 3;
    const float* kr = k + ((size_t)bh * Ss + tglob) * Dd + 16 * ks + 2 * tig;
    float2 p0 = *(const float2*)kr;
    float2 p1 = *(const float2*)(kr + 8);
    int kt = tglob >> 6;
    int tl = tglob & 63;
    int j = tl >> 3, g = tl & 7;
    gK2[((size_t)bh * 32 + kt) * TILE_U2 + (ks * 8 + j) * 32 + g * 4 + tig] =
        make_uint2(packf16(p0.x, p0.y), packf16(p1.x, p1.y));
}

__global__ void split_vt_kernel(const float* __restrict__ v)
{
    int idx = blockIdx.x * 256 + threadIdx.x;    // BH*32*16*64
    int d  = idx & 63;
    int gidx = (idx >> 6) & 15;
    int kt = (idx >> 10) & 31;
    int bh = idx >> 15;
    int ks = gidx >> 2, tig = gidx & 3;
    int t0 = kt * 64 + 16 * ks + 2 * tig;
    const float* vb = v + (size_t)bh * Ss * Dd + d;
    float v0 = vb[(size_t)t0 * Dd];
    float v1 = vb[(size_t)(t0 + 1) * Dd];
    float v2 = vb[(size_t)(t0 + 8) * Dd];
    float v3 = vb[(size_t)(t0 + 9) * Dd];
    int j = d >> 3, g = d & 7;
    gV2[((size_t)bh * 32 + kt) * TILE_U2 + (ks * 8 + j) * 32 + g * 4 + tig] =
        make_uint2(packf16(v0, v1), packf16(v2, v3));
}

// ---------------- smem: 3-stage ring, stage = [K 8KB][V 8KB] ----------------
#define SINV 49152u
#define SMEM_TOTAL (49152 + 512)

__global__ void __launch_bounds__(256, 2)
sdpa_main_kernel(const float* __restrict__ q, float* __restrict__ out)
{
    extern __shared__ char smc[];
    const uint32_t sb = smem_u32(smc);
    float* sInv = (float*)(smc + SINV);

    const int tid  = threadIdx.x;
    const int lane = tid & 31;
    const int w    = tid >> 5;
    const int g    = lane >> 2;
    const int tig  = lane & 3;

    const int bh = blockIdx.y;
    const int b  = bh >> 4;
    const int s0 = blockIdx.x * 128;

    const float* qg = q + ((size_t)bh * Ss + s0) * Dd;
    float* outg = out + ((size_t)bh * Ss + s0) * Dd;
    float* attg = out + (size_t)BH * Ss * Dd + ((size_t)bh * Ss + s0) * Ss;

    const size_t tilebase = (size_t)bh * 32;

    auto issue = [&](int kt) {
        uint32_t dstb = sb + (uint32_t)(kt % 3) * 16384u;
        const char* srcK = (const char*)(gK2 + (tilebase + kt) * TILE_U2);
        const char* srcV = (const char*)(gV2 + (tilebase + kt) * TILE_U2);
        #pragma unroll
        for (int i = 0; i < 2; ++i) {
            int off = (tid + i * 256) * 16;
            asm volatile("cp.async.cg.shared.global [%0], [%1], 16;"
                         :: "r"(dstb + off), "l"(srcK + off));
        }
        #pragma unroll
        for (int i = 0; i < 2; ++i) {
            int off = (tid + i * 256) * 16;
            asm volatile("cp.async.cg.shared.global [%0], [%1], 16;"
                         :: "r"(dstb + 8192u + off), "l"(srcV + off));
        }
        asm volatile("cp.async.commit_group;");
    };

    issue(0);
    issue(1);

    // ---- Q fragments: fp16 hi + lo (exact 2-split), direct gmem loads ----
    const int r0 = w * 16 + g;
    uint2 qh[4][2], ql[4][2];
    {
        const float* q0 = qg + (size_t)r0 * Dd;
        const float* q8 = qg + (size_t)(r0 + 8) * Dd;
        #pragma unroll
        for (int ks = 0; ks < 4; ++ks) {
            int c = 16 * ks + 2 * tig;
            #pragma unroll
            for (int half = 0; half < 2; ++half) {
                const float* qr = half ? q8 : q0;
                float2 p0 = *(const float2*)(qr + c);
                float2 p1 = *(const float2*)(qr + c + 8);
                float h00, h01, h10, h11;
                uint32_t b0h = packf16hi(p0.x, p0.y, h00, h01);
                uint32_t b1h = packf16hi(p1.x, p1.y, h10, h11);
                qh[ks][half] = make_uint2(b0h, b1h);
                ql[ks][half] = make_uint2(packf16(p0.x - h00, p0.y - h01),
                                          packf16(p1.x - h10, p1.y - h11));
            }
        }
    }

    const ull* m64 = (const ull*)g_maskbits;
    const size_t mrow0 = ((size_t)b * Ss + s0 + r0) * (Ss / 64);
    const size_t mrow1 = mrow0 + 8 * (Ss / 64);

    float rs0 = 0.f, rs1 = 0.f;
    float4 po[8];
    #pragma unroll
    for (int j = 0; j < 8; ++j) po[j] = make_float4(0.f, 0.f, 0.f, 0.f);

    float* att0 = attg + (size_t)r0 * Ss;
    float* att1 = attg + (size_t)(r0 + 8) * Ss;

    for (int kt = 0; kt < 32; ++kt) {
        if (kt < 31) { asm volatile("cp.async.wait_group 1;"); }
        else         { asm volatile("cp.async.wait_group 0;"); }
        __syncthreads();
        if (kt < 30) issue(kt + 2);

        const uint2* kb2 = (const uint2*)(smc + (kt % 3) * 16384);
        const uint2* vb2 = kb2 + 1024;

        ull mw0 = m64[mrow0 + kt];
        ull mw1 = m64[mrow1 + kt];

        // ---- QK: 128x64 scores via fp16 2-split (2 mma per step) ----
        float4 cf[8];
        #pragma unroll
        for (int j = 0; j < 8; ++j) cf[j] = make_float4(0.f, 0.f, 0.f, 0.f);

        #pragma unroll
        for (int ks = 0; ks < 4; ++ks) {
            uint2 aH0 = qh[ks][0], aH8 = qh[ks][1];
            uint2 aL0 = ql[ks][0], aL8 = ql[ks][1];
            #pragma unroll
            for (int j = 0; j < 8; ++j) {
                uint2 f = kb2[(ks * 8 + j) * 32 + lane];
                mma16f(cf[j], aH0.x, aH8.x, aH0.y, aH8.y, f.x, f.y);
                mma16f(cf[j], aL0.x, aL8.x, aL0.y, aL8.y, f.x, f.y);
            }
        }

        // ---- epilogue fused with PV (C-frag -> A-frag identity, fp16 2-split) ----
        const int t0k = kt * 64;
        #pragma unroll
        for (int ks2 = 0; ks2 < 4; ++ks2) {
            uint32_t pah[2], pal[2], pbh[2], pbl[2];
            #pragma unroll
            for (int u = 0; u < 2; ++u) {
                int j = 2 * ks2 + u;
                int c0 = 8 * j + 2 * tig;
                float4 c = cf[j];
                float s00 = ((mw0 >> c0) & 1ull)       ? c.x * SCALE : -1e-12f;
                float s01 = ((mw0 >> (c0 + 1)) & 1ull) ? c.y * SCALE : -1e-12f;
                float s10 = ((mw1 >> c0) & 1ull)       ? c.z * SCALE : -1e-12f;
                float s11 = ((mw1 >> (c0 + 1)) & 1ull) ? c.w * SCALE : -1e-12f;
                float e00 = ex2m(s00 * L2E), e01 = ex2m(s01 * L2E);
                float e10 = ex2m(s10 * L2E), e11 = ex2m(s11 * L2E);
                rs0 += e00 + e01; rs1 += e10 + e11;
                *(float2*)(att0 + t0k + c0) = make_float2(e00, e01);
                *(float2*)(att1 + t0k + c0) = make_float2(e10, e11);
                float h0, h1;
                pah[u] = packf16hi(s00, s01, h0, h1);
                pal[u] = packf16(s00 - h0, s01 - h1);
                pbh[u] = packf16hi(s10, s11, h0, h1);
                pbl[u] = packf16(s10 - h0, s11 - h1);
            }
            #pragma unroll
            for (int j = 0; j < 8; ++j) {
                uint2 f = vb2[(ks2 * 8 + j) * 32 + lane];
                mma16f(po[j], pah[0], pbh[0], pah[1], pbh[1], f.x, f.y);
                mma16f(po[j], pal[0], pbl[0], pal[1], pbl[1], f.x, f.y);
            }
        }
        __syncthreads();   // all warps done with stage (kt%3) before refill
    }

    // ---- write output ----
    #pragma unroll
    for (int j = 0; j < 8; ++j) {
        int c0 = 8 * j + 2 * tig;
        *(float2*)(outg + (size_t)r0 * Dd + c0)       = make_float2(po[j].x, po[j].y);
        *(float2*)(outg + (size_t)(r0 + 8) * Dd + c0) = make_float2(po[j].z, po[j].w);
    }

    // ---- rowsum reduce + normalize att ----
    rs0 += __shfl_xor_sync(0xFFFFFFFFu, rs0, 1);
    rs0 += __shfl_xor_sync(0xFFFFFFFFu, rs0, 2);
    rs1 += __shfl_xor_sync(0xFFFFFFFFu, rs1, 1);
    rs1 += __shfl_xor_sync(0xFFFFFFFFu, rs1, 2);
    if (tig == 0) {
        sInv[r0]     = 1.f / rs0;
        sInv[r0 + 8] = 1.f / rs1;
    }
    __syncthreads();

    for (int r = 0; r < 128; ++r) {
        float iv = sInv[r];
        float* row = attg + (size_t)r * Ss + tid * 8;
        float4 a = *(const float4*)(row);
        float4 c = *(const float4*)(row + 4);
        a.x *= iv; a.y *= iv; a.z *= iv; a.w *= iv;
        c.x *= iv; c.y *= iv; c.z *= iv; c.w *= iv;
        *(float4*)(row)     = a;
        *(float4*)(row + 4) = c;
    }
}

extern "C" void kernel_launch(void* const* d_in, const int* in_sizes, int n_in,
                              void* d_out, int out_size)
{
    const float* q = (const float*)d_in[0];
    const float* k = (const float*)d_in[1];
    const float* v = (const float*)d_in[2];
    const int* masks = (const int*)d_in[3];
    float* out = (float*)d_out;

    pack_mask_kernel<<<(Bb * Ss * Ss) / 256, 256>>>(masks);
    split_k_kernel<<<(BH * Ss * 16) / 256, 256>>>(k);
    split_vt_kernel<<<(BH * 32 * 16 * 64) / 256, 256>>>(v);

    cudaFuncSetAttribute(sdpa_main_kernel,
                         cudaFuncAttributeMaxDynamicSharedMemorySize, SMEM_TOTAL);

    dim3 grid(Ss / 128, BH);   // (16, 32)
    sdpa_main_kernel<<<grid, 256, SMEM_TOTAL>>>(q, out);
}

// round 12
// speedup vs baseline: 3.6773x; 1.1370x over previous
#include <cuda_runtime.h>
#include <cstdint>

#define Bb 2
#define Hh 16
#define Ss 2048
#define Dd 64
#define BH (Bb*Hh)
#define SCALE 0.125f

typedef unsigned long long ull;

// ---------------- global scratch ----------------
__device__ unsigned int g_maskbits[(size_t)Bb * Ss * Ss / 32];
#define TILE_U2 1024      // uint2 granules per 8KB chunk-plane
__device__ uint2 gK2[(size_t)BH * 32 * TILE_U2];   // 8 MB (fp16 pairs)
__device__ uint2 gV2[(size_t)BH * 32 * TILE_U2];   // 8 MB

__global__ void pack_mask_kernel(const int* __restrict__ masks)
{
    int e = blockIdx.x * 256 + threadIdx.x;
    int val = masks[e] != 0;
    unsigned bal = __ballot_sync(0xFFFFFFFFu, val);
    if ((threadIdx.x & 31) == 0) g_maskbits[e >> 5] = bal;
}

// ---------------- helpers ----------------
__device__ __forceinline__ uint32_t smem_u32(const void* p) {
    uint32_t a;
    asm("{ .reg .u64 t; cvta.to.shared.u64 t, %1; cvt.u32.u64 %0, t; }" : "=r"(a) : "l"(p));
    return a;
}
// fp16x2 pack: low half = s0, high half = s1
__device__ __forceinline__ uint32_t packf16(float s0, float s1) {
    uint32_t p;
    asm("cvt.rn.f16x2.f32 %0, %1, %2;" : "=r"(p) : "f"(s1), "f"(s0));
    return p;
}
__device__ __forceinline__ void mma16f(float4& d, uint32_t a0, uint32_t a1, uint32_t a2,
                                       uint32_t a3, uint32_t b0, uint32_t b1)
{
    asm volatile(
        "mma.sync.aligned.m16n8k16.row.col.f32.f16.f16.f32 "
        "{%0,%1,%2,%3}, {%4,%5,%6,%7}, {%8,%9}, {%0,%1,%2,%3};"
        : "+f"(d.x), "+f"(d.y), "+f"(d.z), "+f"(d.w)
        : "r"(a0), "r"(a1), "r"(a2), "r"(a3), "r"(b0), "r"(b1));
}
__device__ __forceinline__ float ex2m(float x) {
    float r;
    asm("ex2.approx.f32 %0, %1;" : "=f"(r) : "f"(x));
    return r;
}
#define L2E 1.4426950408889634f

// ---------------- prepasses: fp16 fragment-major granules ----------------
__global__ void split_k_kernel(const float* __restrict__ k)
{
    int idx = blockIdx.x * 256 + threadIdx.x;    // BH*2048*16
    int gidx = idx & 15;
    int tglob = (idx >> 4) & 2047;
    int bh = idx >> 15;
    int ks = gidx >> 2, tig = gidx & 3;
    const float* kr = k + ((size_t)bh * Ss + tglob) * Dd + 16 * ks + 2 * tig;
    float2 p0 = *(const float2*)kr;
    float2 p1 = *(const float2*)(kr + 8);
    int kt = tglob >> 6;
    int tl = tglob & 63;
    int j = tl >> 3, g = tl & 7;
    gK2[((size_t)bh * 32 + kt) * TILE_U2 + (ks * 8 + j) * 32 + g * 4 + tig] =
        make_uint2(packf16(p0.x, p0.y), packf16(p1.x, p1.y));
}

__global__ void split_vt_kernel(const float* __restrict__ v)
{
    int idx = blockIdx.x * 256 + threadIdx.x;    // BH*32*16*64
    int d  = idx & 63;
    int gidx = (idx >> 6) & 15;
    int kt = (idx >> 10) & 31;
    int bh = idx >> 15;
    int ks = gidx >> 2, tig = gidx & 3;
    int t0 = kt * 64 + 16 * ks + 2 * tig;
    const float* vb = v + (size_t)bh * Ss * Dd + d;
    float v0 = vb[(size_t)t0 * Dd];
    float v1 = vb[(size_t)(t0 + 1) * Dd];
    float v2 = vb[(size_t)(t0 + 8) * Dd];
    float v3 = vb[(size_t)(t0 + 9) * Dd];
    int j = d >> 3, g = d & 7;
    gV2[((size_t)bh * 32 + kt) * TILE_U2 + (ks * 8 + j) * 32 + g * 4 + tig] =
        make_uint2(packf16(v0, v1), packf16(v2, v3));
}

// ---------------- smem: 3-stage ring, stage = [K 8KB][V 8KB] ----------------
#define SINV 49152u
#define SMEM_TOTAL (49152 + 512)

__global__ void __launch_bounds__(256, 2)
sdpa_main_kernel(const float* __restrict__ q, float* __restrict__ out)
{
    extern __shared__ char smc[];
    const uint32_t sb = smem_u32(smc);
    float* sInv = (float*)(smc + SINV);

    const int tid  = threadIdx.x;
    const int lane = tid & 31;
    const int w    = tid >> 5;
    const int g    = lane >> 2;
    const int tig  = lane & 3;

    const int bh = blockIdx.y;
    const int b  = bh >> 4;
    const int s0 = blockIdx.x * 128;

    const float* qg = q + ((size_t)bh * Ss + s0) * Dd;
    float* outg = out + ((size_t)bh * Ss + s0) * Dd;
    float* attg = out + (size_t)BH * Ss * Dd + ((size_t)bh * Ss + s0) * Ss;

    const size_t tilebase = (size_t)bh * 32;

    auto issue = [&](int kt) {
        uint32_t dstb = sb + (uint32_t)(kt % 3) * 16384u;
        const char* srcK = (const char*)(gK2 + (tilebase + kt) * TILE_U2);
        const char* srcV = (const char*)(gV2 + (tilebase + kt) * TILE_U2);
        #pragma unroll
        for (int i = 0; i < 2; ++i) {
            int off = (tid + i * 256) * 16;
            asm volatile("cp.async.cg.shared.global [%0], [%1], 16;"
                         :: "r"(dstb + off), "l"(srcK + off));
        }
        #pragma unroll
        for (int i = 0; i < 2; ++i) {
            int off = (tid + i * 256) * 16;
            asm volatile("cp.async.cg.shared.global [%0], [%1], 16;"
                         :: "r"(dstb + 8192u + off), "l"(srcV + off));
        }
        asm volatile("cp.async.commit_group;");
    };

    issue(0);
    issue(1);

    // ---- Q fragments: fp16-rounded, direct gmem loads (one-time) ----
    const int r0 = w * 16 + g;
    uint2 qh[4][2];
    {
        const float* q0 = qg + (size_t)r0 * Dd;
        const float* q8 = qg + (size_t)(r0 + 8) * Dd;
        #pragma unroll
        for (int ks = 0; ks < 4; ++ks) {
            int c = 16 * ks + 2 * tig;
            #pragma unroll
            for (int half = 0; half < 2; ++half) {
                const float* qr = half ? q8 : q0;
                float2 p0 = *(const float2*)(qr + c);
                float2 p1 = *(const float2*)(qr + c + 8);
                qh[ks][half] = make_uint2(packf16(p0.x, p0.y), packf16(p1.x, p1.y));
            }
        }
    }

    const ull* m64 = (const ull*)g_maskbits;
    const size_t mrow0 = ((size_t)b * Ss + s0 + r0) * (Ss / 64);
    const size_t mrow1 = mrow0 + 8 * (Ss / 64);

    float rs0 = 0.f, rs1 = 0.f;
    float4 po[8];
    #pragma unroll
    for (int j = 0; j < 8; ++j) po[j] = make_float4(0.f, 0.f, 0.f, 0.f);

    float* att0 = attg + (size_t)r0 * Ss;
    float* att1 = attg + (size_t)(r0 + 8) * Ss;

    for (int kt = 0; kt < 32; ++kt) {
        if (kt < 31) { asm volatile("cp.async.wait_group 1;"); }
        else         { asm volatile("cp.async.wait_group 0;"); }
        __syncthreads();
        if (kt < 30) issue(kt + 2);

        const uint2* kb2 = (const uint2*)(smc + (kt % 3) * 16384);
        const uint2* vb2 = kb2 + 1024;

        ull mw0 = m64[mrow0 + kt];
        ull mw1 = m64[mrow1 + kt];

        // ---- QK: 128x64 scores, single fp16 mma per step ----
        float4 cf[8];
        #pragma unroll
        for (int j = 0; j < 8; ++j) cf[j] = make_float4(0.f, 0.f, 0.f, 0.f);

        #pragma unroll
        for (int ks = 0; ks < 4; ++ks) {
            uint2 aH0 = qh[ks][0], aH8 = qh[ks][1];
            #pragma unroll
            for (int j = 0; j < 8; ++j) {
                uint2 f = kb2[(ks * 8 + j) * 32 + lane];
                mma16f(cf[j], aH0.x, aH8.x, aH0.y, aH8.y, f.x, f.y);
            }
        }

        // ---- epilogue fused with PV (C-frag -> A-frag identity, fp16) ----
        const int t0k = kt * 64;
        #pragma unroll
        for (int ks2 = 0; ks2 < 4; ++ks2) {
            uint32_t pah[2], pbh[2];
            #pragma unroll
            for (int u = 0; u < 2; ++u) {
                int j = 2 * ks2 + u;
                int c0 = 8 * j + 2 * tig;
                float4 c = cf[j];
                float s00 = ((mw0 >> c0) & 1ull)       ? c.x * SCALE : -1e-12f;
                float s01 = ((mw0 >> (c0 + 1)) & 1ull) ? c.y * SCALE : -1e-12f;
                float s10 = ((mw1 >> c0) & 1ull)       ? c.z * SCALE : -1e-12f;
                float s11 = ((mw1 >> (c0 + 1)) & 1ull) ? c.w * SCALE : -1e-12f;
                float e00 = ex2m(s00 * L2E), e01 = ex2m(s01 * L2E);
                float e10 = ex2m(s10 * L2E), e11 = ex2m(s11 * L2E);
                rs0 += e00 + e01; rs1 += e10 + e11;
                *(float2*)(att0 + t0k + c0) = make_float2(e00, e01);
                *(float2*)(att1 + t0k + c0) = make_float2(e10, e11);
                pah[u] = packf16(s00, s01);
                pbh[u] = packf16(s10, s11);
            }
            #pragma unroll
            for (int j = 0; j < 8; ++j) {
                uint2 f = vb2[(ks2 * 8 + j) * 32 + lane];
                mma16f(po[j], pah[0], pbh[0], pah[1], pbh[1], f.x, f.y);
            }
        }
        __syncthreads();   // all warps done with stage (kt%3) before refill
    }

    // ---- write output ----
    #pragma unroll
    for (int j = 0; j < 8; ++j) {
        int c0 = 8 * j + 2 * tig;
        *(float2*)(outg + (size_t)r0 * Dd + c0)       = make_float2(po[j].x, po[j].y);
        *(float2*)(outg + (size_t)(r0 + 8) * Dd + c0) = make_float2(po[j].z, po[j].w);
    }

    // ---- rowsum reduce + normalize att ----
    rs0 += __shfl_xor_sync(0xFFFFFFFFu, rs0, 1);
    rs0 += __shfl_xor_sync(0xFFFFFFFFu, rs0, 2);
    rs1 += __shfl_xor_sync(0xFFFFFFFFu, rs1, 1);
    rs1 += __shfl_xor_sync(0xFFFFFFFFu, rs1, 2);
    if (tig == 0) {
        sInv[r0]     = 1.f / rs0;
        sInv[r0 + 8] = 1.f / rs1;
    }
    __syncthreads();

    for (int r = 0; r < 128; ++r) {
        float iv = sInv[r];
        float* row = attg + (size_t)r * Ss + tid * 8;
        float4 a = *(const float4*)(row);
        float4 c = *(const float4*)(row + 4);
        a.x *= iv; a.y *= iv; a.z *= iv; a.w *= iv;
        c.x *= iv; c.y *= iv; c.z *= iv; c.w *= iv;
        *(float4*)(row)     = a;
        *(float4*)(row + 4) = c;
    }
}

extern "C" void kernel_launch(void* const* d_in, const int* in_sizes, int n_in,
                              void* d_out, int out_size)
{
    const float* q = (const float*)d_in[0];
    const float* k = (const float*)d_in[1];
    const float* v = (const float*)d_in[2];
    const int* masks = (const int*)d_in[3];
    float* out = (float*)d_out;

    pack_mask_kernel<<<(Bb * Ss * Ss) / 256, 256>>>(masks);
    split_k_kernel<<<(BH * Ss * 16) / 256, 256>>>(k);
    split_vt_kernel<<<(BH * 32 * 16 * 64) / 256, 256>>>(v);

    cudaFuncSetAttribute(sdpa_main_kernel,
                         cudaFuncAttributeMaxDynamicSharedMemorySize, SMEM_TOTAL);

    dim3 grid(Ss / 128, BH);   // (16, 32)
    sdpa_main_kernel<<<grid, 256, SMEM_TOTAL>>>(q, out);
}